// round 2
// baseline (speedup 1.0000x reference)
#include <cuda_runtime.h>
#include <math.h>

#define NSAMP  131072
#define NDIM   512
#define NCOMP  256
#define NCLASS 8
#define NBIN   100

// Scratch: data0 = data @ wT, overwritten in-place with delta = spline(data0) - data0.
__device__ float g_data0[(size_t)NSAMP * NCOMP];

// ---------------------------------------------------------------------------
// GEMM1: g_data0[M x 256] = data[M x 512] @ wT[512 x 256]   (all row-major)
// 128x128 block tile, 16 k-tile, 256 threads, 8x8 microtile.
// ---------------------------------------------------------------------------
__global__ __launch_bounds__(256) void gemm_data0(
    const float* __restrict__ A,   // data, lda = 512
    const float* __restrict__ B)   // wT,   ldb = 256
{
    __shared__ float As[16][132];
    __shared__ float Bs[16][132];
    const int tid = threadIdx.x;
    const int m0  = blockIdx.x * 128;
    const int n0  = blockIdx.y * 128;
    const int tx  = tid & 15;
    const int ty  = tid >> 4;

    float acc[8][8];
    #pragma unroll
    for (int i = 0; i < 8; ++i)
        #pragma unroll
        for (int j = 0; j < 8; ++j) acc[i][j] = 0.f;

    for (int k0 = 0; k0 < NDIM; k0 += 16) {
        // A tile: 128 rows x 16 k, transposed into As[k][row]
        #pragma unroll
        for (int t = 0; t < 2; ++t) {
            int slot = tid + t * 256;
            int row  = slot >> 2;
            int kg   = (slot & 3) * 4;
            float4 a4 = *(const float4*)&A[(size_t)(m0 + row) * NDIM + k0 + kg];
            As[kg + 0][row] = a4.x;
            As[kg + 1][row] = a4.y;
            As[kg + 2][row] = a4.z;
            As[kg + 3][row] = a4.w;
        }
        // B tile: 16 k x 128 n, direct
        #pragma unroll
        for (int t = 0; t < 2; ++t) {
            int slot = tid + t * 256;
            int k    = slot >> 5;
            int ng   = (slot & 31) * 4;
            *(float4*)&Bs[k][ng] = *(const float4*)&B[(size_t)(k0 + k) * NCOMP + n0 + ng];
        }
        __syncthreads();
        #pragma unroll
        for (int kk = 0; kk < 16; ++kk) {
            float a[8], b[8];
            *(float4*)&a[0] = *(float4*)&As[kk][ty * 4];
            *(float4*)&a[4] = *(float4*)&As[kk][64 + ty * 4];
            *(float4*)&b[0] = *(float4*)&Bs[kk][tx * 4];
            *(float4*)&b[4] = *(float4*)&Bs[kk][64 + tx * 4];
            #pragma unroll
            for (int i = 0; i < 8; ++i)
                #pragma unroll
                for (int j = 0; j < 8; ++j)
                    acc[i][j] = fmaf(a[i], b[j], acc[i][j]);
        }
        __syncthreads();
    }

    #pragma unroll
    for (int i = 0; i < 8; ++i) {
        int row = m0 + ((i < 4) ? (ty * 4 + i) : (64 + ty * 4 + (i - 4)));
        float4 v0 = make_float4(acc[i][0], acc[i][1], acc[i][2], acc[i][3]);
        float4 v1 = make_float4(acc[i][4], acc[i][5], acc[i][6], acc[i][7]);
        *(float4*)&g_data0[(size_t)row * NCOMP + n0 + tx * 4]      = v0;
        *(float4*)&g_data0[(size_t)row * NCOMP + n0 + 64 + tx * 4] = v1;
    }
}

// ---------------------------------------------------------------------------
// Spline: per (sample, component). Reads g_data0, writes delta in place,
// block-reduces logd into logj. One block (256 threads) per sample.
// ---------------------------------------------------------------------------
__global__ __launch_bounds__(256) void spline_kernel(
    const float* __restrict__ kx,
    const float* __restrict__ ky,
    const float* __restrict__ kd,
    const int*   __restrict__ label,
    float* __restrict__ logj)
{
    const int n = blockIdx.x;
    const int j = threadIdx.x;
    const int c = label[n];

    const size_t base = ((size_t)c * NCOMP + j) * NBIN;
    const float* __restrict__ xk = kx + base;
    const float* __restrict__ yk = ky + base;
    const float* __restrict__ dk = kd + base;

    const size_t idx0 = (size_t)n * NCOMP + j;
    const float x = g_data0[idx0];

    // lower_bound (searchsorted side='left'): first i with xk[i] >= x
    int lo = 0, hi = NBIN;
    while (lo < hi) {
        int mid = (lo + hi) >> 1;
        if (xk[mid] < x) lo = mid + 1; else hi = mid;
    }

    float y, ld;
    if (lo == 0) {
        float de = dk[0];
        y  = yk[0] + de * (x - xk[0]);
        ld = logf(de);
    } else if (lo == NBIN) {
        float de = dk[NBIN - 1];
        y  = yk[NBIN - 1] + de * (x - xk[NBIN - 1]);
        ld = logf(de);
    } else {
        int k = lo - 1;
        float x0 = xk[k], x1 = xk[k + 1];
        float y0 = yk[k], y1 = yk[k + 1];
        float da = dk[k], db = dk[k + 1];
        float w  = x1 - x0;
        float s  = (y1 - y0) / w;
        float xi = (x - x0) / w;
        xi = fminf(fmaxf(xi, 0.f), 1.f);
        float xi1 = 1.f - xi;
        float denom = s + (da + db - 2.f * s) * xi * xi1;
        y  = y0 + (y1 - y0) * (s * xi * xi + da * xi * xi1) / denom;
        ld = 2.f * logf(s)
           + logf(db * xi * xi + 2.f * s * xi * xi1 + da * xi1 * xi1)
           - 2.f * logf(denom);
    }

    g_data0[idx0] = y - x;   // delta

    // block reduction of ld -> logj[n]
    #pragma unroll
    for (int off = 16; off > 0; off >>= 1)
        ld += __shfl_down_sync(0xFFFFFFFFu, ld, off);
    __shared__ float wsum[8];
    if ((j & 31) == 0) wsum[j >> 5] = ld;
    __syncthreads();
    if (j < 8) {
        float v = wsum[j];
        #pragma unroll
        for (int off = 4; off > 0; off >>= 1)
            v += __shfl_down_sync(0xFFu, v, off);
        if (j == 0) logj[n] = v;
    }
}

// ---------------------------------------------------------------------------
// GEMM2: out[M x 512] = data[M x 512] + delta[M x 256] @ wT^T[256 x 512]
// B-tile is wT accessed transposed (wT[n][k]), transposed into smem.
// ---------------------------------------------------------------------------
__global__ __launch_bounds__(256) void gemm_out(
    const float* __restrict__ W,   // wT, [512 x 256] row-major (used transposed)
    const float* __restrict__ D,   // data, ldd = 512
    float* __restrict__ C)         // out,  ldc = 512
{
    __shared__ float As[16][132];
    __shared__ float Bs[16][132];
    const int tid = threadIdx.x;
    const int m0  = blockIdx.x * 128;
    const int n0  = blockIdx.y * 128;
    const int tx  = tid & 15;
    const int ty  = tid >> 4;

    float acc[8][8];
    #pragma unroll
    for (int i = 0; i < 8; ++i)
        #pragma unroll
        for (int j = 0; j < 8; ++j) acc[i][j] = 0.f;

    for (int k0 = 0; k0 < NCOMP; k0 += 16) {
        // A tile: delta 128 rows x 16 k -> As[k][row]
        #pragma unroll
        for (int t = 0; t < 2; ++t) {
            int slot = tid + t * 256;
            int row  = slot >> 2;
            int kg   = (slot & 3) * 4;
            float4 a4 = *(const float4*)&g_data0[(size_t)(m0 + row) * NCOMP + k0 + kg];
            As[kg + 0][row] = a4.x;
            As[kg + 1][row] = a4.y;
            As[kg + 2][row] = a4.z;
            As[kg + 3][row] = a4.w;
        }
        // B tile: Bs[k][n] = wT[(n0+n)*256 + k0+k]; vector load along k, transpose
        #pragma unroll
        for (int t = 0; t < 2; ++t) {
            int slot = tid + t * 256;
            int nl   = slot >> 2;
            int kg   = (slot & 3) * 4;
            float4 b4 = *(const float4*)&W[(size_t)(n0 + nl) * NCOMP + k0 + kg];
            Bs[kg + 0][nl] = b4.x;
            Bs[kg + 1][nl] = b4.y;
            Bs[kg + 2][nl] = b4.z;
            Bs[kg + 3][nl] = b4.w;
        }
        __syncthreads();
        #pragma unroll
        for (int kk = 0; kk < 16; ++kk) {
            float a[8], b[8];
            *(float4*)&a[0] = *(float4*)&As[kk][ty * 4];
            *(float4*)&a[4] = *(float4*)&As[kk][64 + ty * 4];
            *(float4*)&b[0] = *(float4*)&Bs[kk][tx * 4];
            *(float4*)&b[4] = *(float4*)&Bs[kk][64 + tx * 4];
            #pragma unroll
            for (int i = 0; i < 8; ++i)
                #pragma unroll
                for (int j = 0; j < 8; ++j)
                    acc[i][j] = fmaf(a[i], b[j], acc[i][j]);
        }
        __syncthreads();
    }

    #pragma unroll
    for (int i = 0; i < 8; ++i) {
        int row = m0 + ((i < 4) ? (ty * 4 + i) : (64 + ty * 4 + (i - 4)));
        size_t o0 = (size_t)row * NDIM + n0 + tx * 4;
        size_t o1 = (size_t)row * NDIM + n0 + 64 + tx * 4;
        float4 d0 = *(const float4*)&D[o0];
        float4 d1 = *(const float4*)&D[o1];
        float4 v0 = make_float4(acc[i][0] + d0.x, acc[i][1] + d0.y,
                                acc[i][2] + d0.z, acc[i][3] + d0.w);
        float4 v1 = make_float4(acc[i][4] + d1.x, acc[i][5] + d1.y,
                                acc[i][6] + d1.z, acc[i][7] + d1.w);
        *(float4*)&C[o0] = v0;
        *(float4*)&C[o1] = v1;
    }
}

extern "C" void kernel_launch(void* const* d_in, const int* in_sizes, int n_in,
                              void* d_out, int out_size) {
    const float* data  = (const float*)d_in[0];
    const float* wT    = (const float*)d_in[1];
    const float* kx    = (const float*)d_in[2];
    const float* ky    = (const float*)d_in[3];
    const float* kd    = (const float*)d_in[4];
    const int*   label = (const int*)d_in[5];

    float* out  = (float*)d_out;                       // (N, NDIM) flattened
    float* logj = out + (size_t)NSAMP * NDIM;          // (N,) appended

    dim3 g1(NSAMP / 128, NCOMP / 128);   // (1024, 2)
    gemm_data0<<<g1, 256>>>(data, wT);

    spline_kernel<<<NSAMP, 256>>>(kx, ky, kd, label, logj);

    dim3 g2(NSAMP / 128, NDIM / 128);    // (1024, 4)
    gemm_out<<<g2, 256>>>(wT, data, out);
}

// round 6
// speedup vs baseline: 1.8662x; 1.8662x over previous
#include <cuda_runtime.h>
#include <math.h>
#include <stdint.h>

#define NSAMP  131072
#define NDIM   512
#define NCOMP  256
#define NCLASS 8
#define NBIN   100

// ---------------- scratch (__device__ globals; no allocs) ------------------
// NOTE: device symbols are ONLY referenced from device code. Passing them as
// kernel arguments from host resolves to the host shadow address (and on
// GB300, ATS makes that silently writable from the GPU — R5's 8e-2 bug).
__device__ float g_data0[(size_t)NSAMP * NCOMP];        // data0 -> delta (in place)
__device__ float g_B1[(size_t)NCOMP * 3 * NDIM];        // 256 x 1536 augmented wT^T
__device__ float g_B2[(size_t)NDIM * 3 * NCOMP];        // 512 x 768 augmented wT
__device__ float g_ktx[NCLASS * NBIN * NCOMP];          // knots transposed [c][t][j]
__device__ float g_kty[NCLASS * NBIN * NCOMP];
__device__ float g_ktd[NCLASS * NBIN * NCOMP];
__device__ int   g_idx[NSAMP];
__device__ int   g_cnt[NCLASS];
__device__ int   g_off[NCLASS];
__device__ int   g_cur[NCLASS];

// ---------------- small helpers --------------------------------------------
__device__ __forceinline__ float tf32_rna(float v) {
    uint32_t r;
    asm("cvt.rna.tf32.f32 %0, %1;" : "=r"(r) : "f"(v));
    return __uint_as_float(r);
}
__device__ __forceinline__ void cp16(void* s, const void* g) {
    uint32_t sa = (uint32_t)__cvta_generic_to_shared(s);
    asm volatile("cp.async.ca.shared.global [%0], [%1], 16;" :: "r"(sa), "l"(g));
}
#define CP_COMMIT() asm volatile("cp.async.commit_group;" ::: "memory")
#define CP_WAIT0()  asm volatile("cp.async.wait_group 0;" ::: "memory")

__device__ __forceinline__ void mma8(float* c, const uint32_t* a, const uint32_t* b) {
    asm volatile(
        "mma.sync.aligned.m16n8k8.row.col.f32.tf32.tf32.f32 "
        "{%0,%1,%2,%3}, {%4,%5,%6,%7}, {%8,%9}, {%0,%1,%2,%3};"
        : "+f"(c[0]), "+f"(c[1]), "+f"(c[2]), "+f"(c[3])
        : "r"(a[0]), "r"(a[1]), "r"(a[2]), "r"(a[3]), "r"(b[0]), "r"(b[1]));
}

// ---------------- prep: wT -> augmented 3xTF32 operand layouts -------------
// Augmented chunk (48 cols per 16 source k): seg0 = hh, seg1 = lo_a*hi_b,
// seg2 = hi_a*lo_b.  A stores [hi,lo,hi]; B stores [hi,hi,lo].  Within each
// 16, two k8 groups, each permuted [0,4,1,5,2,6,3,7] so fragment pairs
// (k, k+4) are adjacent (one 64-bit LDS per fragment).
__global__ void prep_wt(const float* __restrict__ wT) {
    int e = blockIdx.x * 256 + threadIdx.x;    // over 512*256
    int r = e >> 8, c = e & 255;               // r: dim, c: comp
    float v  = wT[e];
    float hi = tf32_rna(v);
    float lo = tf32_rna(v - hi);
    {   // B1 row n=c (comp), k=r (dim): value wT[r][c]
        int ci = r >> 4, j = r & 15, jj = j & 7;
        int p  = (jj < 4) ? 2 * jj : 2 * jj - 7;
        int col = ((j >> 3) << 3) + p;
        size_t base = (size_t)c * 1536 + ci * 48 + col;
        g_B1[base] = hi; g_B1[base + 16] = hi; g_B1[base + 32] = lo;
    }
    {   // B2 row n=r (dim), k=c (comp): value wT[r][c]
        int ci = c >> 4, j = c & 15, jj = j & 7;
        int p  = (jj < 4) ? 2 * jj : 2 * jj - 7;
        int col = ((j >> 3) << 3) + p;
        size_t base = (size_t)r * 768 + ci * 48 + col;
        g_B2[base] = hi; g_B2[base + 16] = hi; g_B2[base + 32] = lo;
    }
}

// knots [c][j][t] -> [c][t][j] (coalesced tile loads + conflict-free smem)
__global__ void prep_knots(const float* __restrict__ kx, const float* __restrict__ ky,
                           const float* __restrict__ kd) {
    int e = blockIdx.x * 256 + threadIdx.x;    // 8*100*256
    int c = e / (NBIN * NCOMP);
    int rem = e - c * NBIN * NCOMP;
    int t = rem >> 8, j = rem & 255;
    int src = (c * NCOMP + j) * NBIN + t;
    g_ktx[e] = kx[src]; g_kty[e] = ky[src]; g_ktd[e] = kd[src];
}

// class sort
__global__ void prep_zero() {
    if (threadIdx.x < NCLASS) { g_cnt[threadIdx.x] = 0; g_cur[threadIdx.x] = 0; }
}
__global__ void prep_count(const int* __restrict__ label) {
    atomicAdd(&g_cnt[label[blockIdx.x * 256 + threadIdx.x]], 1);
}
__global__ void prep_off() {
    int o = 0;
    for (int c = 0; c < NCLASS; ++c) { g_off[c] = o; o += g_cnt[c]; }
}
__global__ void prep_scatter(const int* __restrict__ label) {
    int i = blockIdx.x * 256 + threadIdx.x;
    int c = label[i];
    int p = atomicAdd(&g_cur[c], 1);
    g_idx[g_off[c] + p] = i;
}

// ---------------- GEMM staging helpers -------------------------------------
#define ASTRIDE 56
#define BSTRIDE_S 56

template<int LDA>
__device__ __forceinline__ void ldgA(const float* __restrict__ Ag, int m0, int ci,
                                     int tid, float4* a_src) {
    #pragma unroll
    for (int i = 0; i < 2; ++i) {
        int idx = tid + i * 256;
        int row = idx >> 2, fi = idx & 3;
        a_src[i] = *(const float4*)&Ag[(size_t)(m0 + row) * LDA + ci * 16 + fi * 4];
    }
}
__device__ __forceinline__ void stsA(float* __restrict__ Ab, int tid,
                                     const float4* a_src) {
    #pragma unroll
    for (int i = 0; i < 2; ++i) {
        int idx = tid + i * 256;
        int row = idx >> 2, fi = idx & 3;
        const float* v = (const float*)&a_src[i];
        #pragma unroll
        for (int e = 0; e < 4; ++e) {
            int j  = fi * 4 + e, jj = j & 7;
            int p  = (jj < 4) ? 2 * jj : 2 * jj - 7;
            int col = ((j >> 3) << 3) + p;
            float hi = tf32_rna(v[e]);
            float lo = tf32_rna(v[e] - hi);
            Ab[row * ASTRIDE + col]      = hi;
            Ab[row * ASTRIDE + 16 + col] = lo;
            Ab[row * ASTRIDE + 32 + col] = hi;
        }
    }
}
template<int NT, int BSTR>
__device__ __forceinline__ void cpB(const float* __restrict__ Bg, int n0, int ci,
                                    int tid, float* __restrict__ Bb) {
    const float* src = Bg + (size_t)n0 * BSTR + ci * 48;
    #pragma unroll
    for (int i = 0; i < NT / 32; ++i) {
        int idx = tid + i * 256;
        int row = idx >> 3, f = idx & 7;
        cp16(&Bb[row * BSTRIDE_S + f * 4], &src[(size_t)row * BSTR + f * 4]);
    }
    #pragma unroll
    for (int i = 0; i < NT / 64; ++i) {
        int idx = tid + i * 256;
        int row = idx >> 2, f = 8 + (idx & 3);
        cp16(&Bb[row * BSTRIDE_S + f * 4], &src[(size_t)row * BSTR + f * 4]);
    }
}

// ---------------- main GEMM ------------------------------------------------
// EPI=1: g_data0[M,256] = data @ wT           (A=data,    B=g_B1, C=g_data0)
// EPI=2: out[M,512]     = data + delta @ wT^T (A=g_data0, B=g_B2, C=out)
template<int NT, int NCH, int BSTR, int LDA, int EPI>
__global__ __launch_bounds__(256, 1)
void gemm_k(const float* __restrict__ Adat, const float* __restrict__ Dg,
            float* __restrict__ Cg)
{
    constexpr int NTN = NT / 32;             // n-tiles per warp
    constexpr int ASZ = 128 * ASTRIDE;
    constexpr int BSZ = NT * BSTRIDE_S;
    constexpr int SSZ = ASZ + BSZ;
    extern __shared__ float sm[];
    float* Abuf[2] = { sm, sm + SSZ };
    float* Bbuf[2] = { sm + ASZ, sm + SSZ + ASZ };

    const int tid = threadIdx.x, lane = tid & 31, wid = tid >> 5;
    const int lr = lane >> 2, lc = lane & 3;
    const int m0 = blockIdx.x * 128;
    const int n0 = blockIdx.y * NT;
    const int mw = (wid >> 2) * 64;
    const int nw = (wid & 3) * (NT / 4);

    // device-side symbol resolution (NEVER pass __device__ symbols from host)
    const float* Ag = (EPI == 1) ? Adat : (const float*)g_data0;
    const float* Bg = (EPI == 1) ? (const float*)g_B1 : (const float*)g_B2;
    float*       Cp = (EPI == 1) ? (float*)g_data0 : Cg;

    float acc[4][NTN][4];
    #pragma unroll
    for (int mi = 0; mi < 4; ++mi)
        #pragma unroll
        for (int ni = 0; ni < NTN; ++ni)
            #pragma unroll
            for (int q = 0; q < 4; ++q) acc[mi][ni][q] = 0.f;

    float4 a_src[2];

    // prologue: stage chunk 0
    cpB<NT, BSTR>(Bg, n0, 0, tid, Bbuf[0]);
    CP_COMMIT();
    ldgA<LDA>(Ag, m0, 0, tid, a_src);
    stsA(Abuf[0], tid, a_src);
    CP_WAIT0();
    __syncthreads();

    for (int ci = 0; ci < NCH; ++ci) {
        const int cur = ci & 1, nxt = cur ^ 1;
        if (ci + 1 < NCH) {
            cpB<NT, BSTR>(Bg, n0, ci + 1, tid, Bbuf[nxt]);
            CP_COMMIT();
            ldgA<LDA>(Ag, m0, ci + 1, tid, a_src);
        }
        const float* Ab = Abuf[cur];
        const float* Bb = Bbuf[cur];
        #pragma unroll
        for (int g = 0; g < 6; ++g) {
            float2 bf[NTN];
            #pragma unroll
            for (int ni = 0; ni < NTN; ++ni)
                bf[ni] = *(const float2*)&Bb[(nw + ni * 8 + lr) * BSTRIDE_S + g * 8 + 2 * lc];
            #pragma unroll
            for (int mi = 0; mi < 4; ++mi) {
                int ar = mw + mi * 16 + lr;
                float2 a02 = *(const float2*)&Ab[ar * ASTRIDE + g * 8 + 2 * lc];
                float2 a13 = *(const float2*)&Ab[(ar + 8) * ASTRIDE + g * 8 + 2 * lc];
                uint32_t a[4] = { __float_as_uint(a02.x), __float_as_uint(a13.x),
                                  __float_as_uint(a02.y), __float_as_uint(a13.y) };
                #pragma unroll
                for (int ni = 0; ni < NTN; ++ni)
                    mma8(acc[mi][ni], a, (const uint32_t*)&bf[ni]);
            }
        }
        if (ci + 1 < NCH) { stsA(Abuf[nxt], tid, a_src); CP_WAIT0(); }
        __syncthreads();
    }

    // epilogue
    #pragma unroll
    for (int mi = 0; mi < 4; ++mi) {
        int r0 = m0 + mw + mi * 16 + lr;
        #pragma unroll
        for (int ni = 0; ni < NTN; ++ni) {
            int cc = n0 + nw + ni * 8 + 2 * lc;
            if (EPI == 1) {
                *(float2*)&Cp[(size_t)r0 * NCOMP + cc] =
                    make_float2(acc[mi][ni][0], acc[mi][ni][1]);
                *(float2*)&Cp[(size_t)(r0 + 8) * NCOMP + cc] =
                    make_float2(acc[mi][ni][2], acc[mi][ni][3]);
            } else {
                float2 d0 = *(const float2*)&Dg[(size_t)r0 * NDIM + cc];
                float2 d1 = *(const float2*)&Dg[(size_t)(r0 + 8) * NDIM + cc];
                *(float2*)&Cp[(size_t)r0 * NDIM + cc] =
                    make_float2(acc[mi][ni][0] + d0.x, acc[mi][ni][1] + d0.y);
                *(float2*)&Cp[(size_t)(r0 + 8) * NDIM + cc] =
                    make_float2(acc[mi][ni][2] + d1.x, acc[mi][ni][3] + d1.y);
            }
        }
    }
}

// ---------------- spline: class-sorted, smem tables, lane=comp -------------
__global__ __launch_bounds__(256) void spline_kernel(float* __restrict__ logj)
{
    __shared__ float xs[NBIN * 32], ys[NBIN * 32], ds[NBIN * 32];
    __shared__ float acc_s[2080];
    const int tid = threadIdx.x, lane = tid & 31, wid = tid >> 5;
    const int c = blockIdx.x >> 6, b = blockIdx.x & 63;
    const int cnt = g_cnt[c], off = g_off[c];
    const int chunk = (cnt + 63) >> 6;
    const int s0 = b * chunk;
    const int s1 = min(s0 + chunk, cnt);
    const int nloc = s1 - s0;
    if (nloc <= 0) return;
    for (int i = tid; i < nloc; i += 256) acc_s[i] = 0.f;

    for (int tile = 0; tile < 8; ++tile) {
        __syncthreads();
        const int j0 = tile * 32;
        for (int e = tid; e < NBIN * 32; e += 256) {
            int t = e >> 5, j = e & 31;
            int gi = (c * NBIN + t) * NCOMP + j0 + j;
            xs[e] = g_ktx[gi]; ys[e] = g_kty[gi]; ds[e] = g_ktd[gi];
        }
        __syncthreads();

        for (int i = s0 + wid; i < s1; i += 8) {
            const int s = g_idx[off + i];
            const size_t gi = (size_t)s * NCOMP + j0 + lane;
            const float x = g_data0[gi];
            // lower_bound over 100 knots: count of knots < x
            int id = 0;
            #pragma unroll
            for (int stp = 64; stp >= 1; stp >>= 1) {
                int t = id + stp;
                int ta = min(t, NBIN);
                float kv = xs[(ta - 1) * 32 + lane];
                if (t <= NBIN && kv < x) id = t;
            }
            int k = min(max(id - 1, 0), NBIN - 2);
            float x0 = xs[k * 32 + lane], x1 = xs[(k + 1) * 32 + lane];
            float y0 = ys[k * 32 + lane], y1 = ys[(k + 1) * 32 + lane];
            float da = ds[k * 32 + lane], db = ds[(k + 1) * 32 + lane];
            float w  = x1 - x0, dy = y1 - y0;
            float iw = __fdividef(1.f, w);
            float sv = dy * iw;
            float xi = fminf(fmaxf((x - x0) * iw, 0.f), 1.f);
            float xi1 = 1.f - xi;
            float denom = sv + (da + db - 2.f * sv) * xi * xi1;
            float idn = __fdividef(1.f, denom);
            float y_in = y0 + dy * (sv * xi * xi + da * xi * xi1) * idn;
            float num  = db * xi * xi + 2.f * sv * xi * xi1 + da * xi1 * xi1;
            bool below = (id == 0), above = (id == NBIN);
            float arg = below ? da : (above ? db : sv * sv * num * idn * idn);
            float y   = below ? (y0 + da * (x - x0))
                              : (above ? (y1 + db * (x - x1)) : y_in);
            float ld  = __logf(arg);
            g_data0[gi] = y - x;
            #pragma unroll
            for (int o = 16; o; o >>= 1) ld += __shfl_down_sync(0xFFFFFFFFu, ld, o);
            if (lane == 0) acc_s[i - s0] += ld;
        }
    }
    __syncthreads();
    for (int i = tid; i < nloc; i += 256)
        logj[g_idx[off + s0 + i]] = acc_s[i];
}

// ---------------- launch ----------------------------------------------------
extern "C" void kernel_launch(void* const* d_in, const int* in_sizes, int n_in,
                              void* d_out, int out_size) {
    const float* data  = (const float*)d_in[0];
    const float* wT    = (const float*)d_in[1];
    const float* kx    = (const float*)d_in[2];
    const float* ky    = (const float*)d_in[3];
    const float* kd    = (const float*)d_in[4];
    const int*   label = (const int*)d_in[5];

    float* out  = (float*)d_out;                    // (N, NDIM)
    float* logj = out + (size_t)NSAMP * NDIM;       // (N,)

    constexpr int SM1 = 2 * (128 * ASTRIDE + 256 * BSTRIDE_S) * 4;  // 172 KB
    constexpr int SM2 = 2 * (128 * ASTRIDE + 128 * BSTRIDE_S) * 4;  // 114.7 KB
    cudaFuncSetAttribute((const void*)gemm_k<256, 32, 1536, 512, 1>,
                         cudaFuncAttributeMaxDynamicSharedMemorySize, SM1);
    cudaFuncSetAttribute((const void*)gemm_k<128, 16, 768, 256, 2>,
                         cudaFuncAttributeMaxDynamicSharedMemorySize, SM2);

    prep_wt<<<NDIM * NCOMP / 256, 256>>>(wT);
    prep_knots<<<NCLASS * NBIN * NCOMP / 256, 256>>>(kx, ky, kd);
    prep_zero<<<1, 32>>>();
    prep_count<<<NSAMP / 256, 256>>>(label);
    prep_off<<<1, 1>>>();
    prep_scatter<<<NSAMP / 256, 256>>>(label);

    // NB: C pointer for EPI=1 is resolved to g_data0 inside device code.
    gemm_k<256, 32, 1536, 512, 1><<<dim3(NSAMP / 128, 1), 256, SM1>>>(
        data, nullptr, nullptr);

    spline_kernel<<<NCLASS * 64, 256>>>(logj);

    gemm_k<128, 16, 768, 256, 2><<<dim3(NSAMP / 128, NDIM / 128), 256, SM2>>>(
        nullptr, data, out);
}